// round 13
// baseline (speedup 1.0000x reference)
#include <cuda_runtime.h>
#include <math.h>

// GWD loss, single fused kernel (R11 pipeline + balanced tail):
//  - every warp does EXACTLY 5 pipelined 128-row chunks (no ceil-quantization:
//    825 of 2960 warps no longer run a 6th chunk while the rest idle)
//  - remaining 105,600 rows (5.3%) done by a flat grid-stride scalar pass,
//    1-2 rows per thread, balanced to +-1 row
//  - warp-private double-buffered cp.async, no __syncthreads in hot loop
//  - reduced row math: ONE __cosf via trig identity, fused scale into sqrt
//  - block reduce -> g_partials; last finished block reduces, writes mean

#define NBLOCKS   740    // 148 SMs * 5 (45KB smem/block)
#define NTHREADS  128    // 4 warps
#define NWARPS    4
#define WCHUNK    128    // rows per warp-iteration
#define STAGE_F4  352    // pred 160 + targ 160 + wgt 32

__device__ float g_partials[NBLOCKS];
__device__ unsigned int g_count = 0;

__device__ __forceinline__ float f_sqrt(float x) {
    float r; asm("sqrt.approx.f32 %0, %1;" : "=f"(r) : "f"(x)); return r;
}
__device__ __forceinline__ float f_rsqrt(float x) {
    float r; asm("rsqrt.approx.f32 %0, %1;" : "=f"(r) : "f"(x)); return r;
}
__device__ __forceinline__ float f_rcp(float x) {
    float r; asm("rcp.approx.f32 %0, %1;" : "=f"(r) : "f"(x)); return r;
}
__device__ __forceinline__ float f_lg2(float x) {
    float r; asm("lg2.approx.f32 %0, %1;" : "=f"(r) : "f"(x)); return r;
}

__device__ __forceinline__ void cp16(float4* smem, const float4* gmem) {
    unsigned saddr = (unsigned)__cvta_generic_to_shared(smem);
    asm volatile("cp.async.cg.shared.global [%0], [%1], 16;\n"
                 :: "r"(saddr), "l"(gmem));
}

__device__ __forceinline__ float row_loss(
    float xp, float yp, float wp, float hp, float rp,
    float xt, float yt, float wt, float ht, float rt,
    float wgt)
{
    float dx = xp - xt, dy = yp - yt;
    float xyd = dx * dx + dy * dy;

    float wp2 = wp * wp, hp2 = hp * hp;
    float wt2 = wt * wt, ht2 = ht * ht;

    float Sp = 0.125f * (wp2 + hp2);    // tr(Sigma_p)/2
    float Dp = 0.125f * (wp2 - hp2);
    float St = 0.125f * (wt2 + ht2);
    float Dt = 0.125f * (wt2 - ht2);

    float cosd = __cosf(2.0f * (rp - rt));
    float trcross = 2.0f * (Sp * St + Dp * Dt * cosd);

    float prod4 = fabsf(wp * hp * wt * ht);
    float inner = fmaxf(trcross + 0.125f * prod4, 0.0f);

    float whr = 2.0f * ((Sp + St) - f_sqrt(inner));

    float u = fmaxf(xyd + whr, 0.0f);
    float dist = f_sqrt(u * f_rsqrt(prod4));   // sqrt(u)/prod4^(1/4)

    float ln1p = f_lg2(1.0f + dist) * 0.6931471805599453f;
    float loss = 1.0f - f_rcp(1.0f + ln1p);
    return loss * wgt;
}

__global__ __launch_bounds__(NTHREADS, 5)
void gwd_fused_kernel(const float* __restrict__ pred,
                      const float* __restrict__ target,
                      const float* __restrict__ weight,
                      float* __restrict__ out,
                      int n)
{
    // per warp, per stage: [0..159]=pred f4, [160..319]=targ f4, [320..351]=wgt f4
    __shared__ float4 s_buf[NWARPS][2][STAGE_F4];   // 45,056 B

    const int tid  = threadIdx.x;
    const int lane = tid & 31;
    const int warp = tid >> 5;

    const int gw = blockIdx.x * NWARPS + warp;   // global warp id
    const int W  = gridDim.x * NWARPS;           // 2960 warps
    // every warp does exactly K full chunks; remainder handled scalar
    const int K  = n / (W * WCHUNK);             // 5 for N=2M
    const int rows_piped = K * W * WCHUNK;       // 1,894,400

    float acc = 0.0f;

    auto issue = [&](int c, float4* b) {
        const float4* gp  = (const float4*)(pred   + (long)c * WCHUNK * 5);
        const float4* gt  = (const float4*)(target + (long)c * WCHUNK * 5);
        const float4* gwt = (const float4*)(weight + (long)c * WCHUNK);
        #pragma unroll
        for (int k = 0; k < 5; k++)
            cp16(&b[k * 32 + lane], &gp[k * 32 + lane]);
        #pragma unroll
        for (int k = 0; k < 5; k++)
            cp16(&b[160 + k * 32 + lane], &gt[k * 32 + lane]);
        cp16(&b[320 + lane], &gwt[lane]);
    };

    // pipelined phase: chunks gw, gw+W, ..., gw+(K-1)W  (all warps equal)
    if (K > 0) {
        issue(gw, s_buf[warp][0]);
        asm volatile("cp.async.commit_group;\n" ::: "memory");

        int s = 0;
        for (int k = 0; k < K; k++)
        {
            if (k + 1 < K) issue(gw + (k + 1) * W, s_buf[warp][s ^ 1]);
            asm volatile("cp.async.commit_group;\n" ::: "memory");
            asm volatile("cp.async.wait_group 1;\n" ::: "memory");
            __syncwarp();   // cross-lane visibility of stage s

            const float* base = (const float*)s_buf[warp][s];
            #pragma unroll
            for (int j = 0; j < 4; j++) {
                int r = j * 32 + lane;             // conflict-free stride-5
                const float* p = base + 5 * r;
                const float* t = base + 640 + 5 * r;
                float wgt = base[1280 + r];
                acc += row_loss(p[0], p[1], p[2], p[3], p[4],
                                t[0], t[1], t[2], t[3], t[4], wgt);
            }
            __syncwarp();   // done reading stage s before re-issue
            s ^= 1;
        }
    }

    // balanced scalar tail: rows [rows_piped, n), 1-2 rows per thread
    const int nthr = gridDim.x * NTHREADS;       // 94,720 threads
    for (int i = rows_piped + blockIdx.x * NTHREADS + tid; i < n; i += nthr) {
        const float* p = pred   + 5 * (long)i;
        const float* t = target + 5 * (long)i;
        acc += row_loss(p[0], p[1], p[2], p[3], p[4],
                        t[0], t[1], t[2], t[3], t[4], weight[i]);
    }

    // block reduction (barriers only here, outside hot loop)
    __shared__ float s_warp[NWARPS];
    for (int off = 16; off > 0; off >>= 1)
        acc += __shfl_down_sync(0xFFFFFFFFu, acc, off);
    if (lane == 0) s_warp[warp] = acc;
    __syncthreads();

    __shared__ bool s_last;
    if (warp == 0) {
        float v = (lane < NWARPS) ? s_warp[lane] : 0.0f;
        for (int off = 2; off > 0; off >>= 1)
            v += __shfl_down_sync(0xFFFFFFFFu, v, off);
        if (lane == 0) {
            g_partials[blockIdx.x] = v;
            __threadfence();
            unsigned int done = atomicAdd(&g_count, 1u);
            s_last = (done == gridDim.x - 1);
        }
    }
    __syncthreads();

    // last block reduces all partials, vectorized (185 f4 = 740 floats)
    if (s_last) {
        const float4* p4 = (const float4*)g_partials;
        float v = 0.0f;
        int nf4 = NBLOCKS / 4;                     // 185
        for (int k = tid; k < nf4; k += NTHREADS) {
            float4 q = p4[k];
            v += (q.x + q.y) + (q.z + q.w);
        }
        for (int off = 16; off > 0; off >>= 1)
            v += __shfl_down_sync(0xFFFFFFFFu, v, off);
        if (lane == 0) s_warp[warp] = v;
        __syncthreads();
        if (warp == 0) {
            float r = (lane < NWARPS) ? s_warp[lane] : 0.0f;
            for (int off = 2; off > 0; off >>= 1)
                r += __shfl_down_sync(0xFFFFFFFFu, r, off);
            if (lane == 0) {
                out[0] = r / (float)n;
                g_count = 0;   // reset for next graph replay
            }
        }
    }
}

extern "C" void kernel_launch(void* const* d_in, const int* in_sizes, int n_in,
                              void* d_out, int out_size)
{
    const float* pred   = (const float*)d_in[0];
    const float* target = (const float*)d_in[1];
    const float* weight = (const float*)d_in[2];
    float* out = (float*)d_out;

    int n = in_sizes[2];  // weight has N elements

    gwd_fused_kernel<<<NBLOCKS, NTHREADS>>>(pred, target, weight, out, n);
}

// round 14
// speedup vs baseline: 1.0703x; 1.0703x over previous
#include <cuda_runtime.h>
#include <math.h>

// GWD loss, single fused kernel (R11 winner, reconfirmation):
//  - warp-private double-buffered cp.async, 128-row chunks (stage 5632B),
//    11 coalesced 16B cp.async per lane, no __syncthreads in hot loop
//  - 45KB smem/block -> 5 blocks/SM, grid 740 = one wave
//  - reduced row math: tr(St Sp) = 2SpSt + 2DpDt cos(2(rp-rt)) -> ONE __cosf;
//    sqrt(u)/prod^(1/4) = sqrt(u*rsqrt(prod)); approx MUFU ops throughout
//  - block reduce -> g_partials; last finished block reduces, writes mean

#define NBLOCKS   740    // 148 SMs * 5 (45KB smem/block)
#define NTHREADS  128    // 4 warps
#define NWARPS    4
#define WCHUNK    128    // rows per warp-iteration
#define STAGE_F4  352    // pred 160 + targ 160 + wgt 32

__device__ float g_partials[NBLOCKS];
__device__ unsigned int g_count = 0;

__device__ __forceinline__ float f_sqrt(float x) {
    float r; asm("sqrt.approx.f32 %0, %1;" : "=f"(r) : "f"(x)); return r;
}
__device__ __forceinline__ float f_rsqrt(float x) {
    float r; asm("rsqrt.approx.f32 %0, %1;" : "=f"(r) : "f"(x)); return r;
}
__device__ __forceinline__ float f_rcp(float x) {
    float r; asm("rcp.approx.f32 %0, %1;" : "=f"(r) : "f"(x)); return r;
}
__device__ __forceinline__ float f_lg2(float x) {
    float r; asm("lg2.approx.f32 %0, %1;" : "=f"(r) : "f"(x)); return r;
}

__device__ __forceinline__ void cp16(float4* smem, const float4* gmem) {
    unsigned saddr = (unsigned)__cvta_generic_to_shared(smem);
    asm volatile("cp.async.cg.shared.global [%0], [%1], 16;\n"
                 :: "r"(saddr), "l"(gmem));
}

__device__ __forceinline__ float row_loss(
    float xp, float yp, float wp, float hp, float rp,
    float xt, float yt, float wt, float ht, float rt,
    float wgt)
{
    float dx = xp - xt, dy = yp - yt;
    float xyd = dx * dx + dy * dy;

    float wp2 = wp * wp, hp2 = hp * hp;
    float wt2 = wt * wt, ht2 = ht * ht;

    float Sp = 0.125f * (wp2 + hp2);    // tr(Sigma_p)/2
    float Dp = 0.125f * (wp2 - hp2);
    float St = 0.125f * (wt2 + ht2);
    float Dt = 0.125f * (wt2 - ht2);

    float cosd = __cosf(2.0f * (rp - rt));
    // tr(Sigma_t Sigma_p):
    float trcross = 2.0f * (Sp * St + Dp * Dt * cosd);

    float prod4 = fabsf(wp * hp * wt * ht);
    // inner = trcross + 2*sqrt(det(cross)) = trcross + prod4/8
    float inner = fmaxf(trcross + 0.125f * prod4, 0.0f);

    // whr = tr_p + tr_t - 2*sqrt(inner) = 2(Sp+St) - 2*sqrt(inner)
    float whr = 2.0f * ((Sp + St) - f_sqrt(inner));

    float u = fmaxf(xyd + whr, 0.0f);
    // dist = sqrt(u)/prod4^(1/4) = sqrt(u * rsqrt(prod4))
    float dist = f_sqrt(u * f_rsqrt(prod4));

    float ln1p = f_lg2(1.0f + dist) * 0.6931471805599453f;
    float loss = 1.0f - f_rcp(1.0f + ln1p);
    return loss * wgt;
}

__global__ __launch_bounds__(NTHREADS, 5)
void gwd_fused_kernel(const float* __restrict__ pred,
                      const float* __restrict__ target,
                      const float* __restrict__ weight,
                      float* __restrict__ out,
                      int n)
{
    // per warp, per stage: [0..159]=pred f4, [160..319]=targ f4, [320..351]=wgt f4
    __shared__ float4 s_buf[NWARPS][2][STAGE_F4];   // 45,056 B

    const int tid  = threadIdx.x;
    const int lane = tid & 31;
    const int warp = tid >> 5;

    const int gw = blockIdx.x * NWARPS + warp;   // global warp id
    const int W  = gridDim.x * NWARPS;           // total warps
    const int nchunks = n / WCHUNK;              // 15625 for N=2M (exact)

    float acc = 0.0f;

    auto issue = [&](int c, float4* b) {
        const float4* gp  = (const float4*)(pred   + (long)c * WCHUNK * 5);
        const float4* gt  = (const float4*)(target + (long)c * WCHUNK * 5);
        const float4* gwt = (const float4*)(weight + (long)c * WCHUNK);
        #pragma unroll
        for (int k = 0; k < 5; k++)
            cp16(&b[k * 32 + lane], &gp[k * 32 + lane]);
        #pragma unroll
        for (int k = 0; k < 5; k++)
            cp16(&b[160 + k * 32 + lane], &gt[k * 32 + lane]);
        cp16(&b[320 + lane], &gwt[lane]);
    };

    int c = gw;
    if (c < nchunks) issue(c, s_buf[warp][0]);
    asm volatile("cp.async.commit_group;\n" ::: "memory");

    int s = 0;
    for (; c < nchunks; c += W)
    {
        int cn = c + W;
        float4* cur = s_buf[warp][s];
        float4* nxt = s_buf[warp][s ^ 1];
        if (cn < nchunks) issue(cn, nxt);
        asm volatile("cp.async.commit_group;\n" ::: "memory");
        asm volatile("cp.async.wait_group 1;\n" ::: "memory");
        __syncwarp();   // cross-lane visibility of cur

        const float* base = (const float*)cur;
        #pragma unroll
        for (int k = 0; k < 4; k++) {
            int r = k * 32 + lane;                 // conflict-free stride-5
            const float* p = base + 5 * r;
            const float* t = base + 640 + 5 * r;
            float wgt = base[1280 + r];
            acc += row_loss(p[0], p[1], p[2], p[3], p[4],
                            t[0], t[1], t[2], t[3], t[4], wgt);
        }
        __syncwarp();   // done reading cur before it's re-issued
        s ^= 1;
    }

    // tail rows (none for N=2M, kept for generality): block 0 scalar
    int tail_start = nchunks * WCHUNK;
    if (blockIdx.x == 0 && tail_start + tid < n) {
        int i = tail_start + tid;
        const float* p = pred + 5 * (long)i;
        const float* t = target + 5 * (long)i;
        acc += row_loss(p[0], p[1], p[2], p[3], p[4],
                        t[0], t[1], t[2], t[3], t[4], weight[i]);
    }

    // block reduction (barriers only here, outside hot loop)
    __shared__ float s_warp[NWARPS];
    for (int off = 16; off > 0; off >>= 1)
        acc += __shfl_down_sync(0xFFFFFFFFu, acc, off);
    if (lane == 0) s_warp[warp] = acc;
    __syncthreads();

    __shared__ bool s_last;
    if (warp == 0) {
        float v = (lane < NWARPS) ? s_warp[lane] : 0.0f;
        for (int off = 2; off > 0; off >>= 1)
            v += __shfl_down_sync(0xFFFFFFFFu, v, off);
        if (lane == 0) {
            g_partials[blockIdx.x] = v;
            __threadfence();
            unsigned int done = atomicAdd(&g_count, 1u);
            s_last = (done == gridDim.x - 1);
        }
    }
    __syncthreads();

    // last block reduces all partials, vectorized (185 f4 = 740 floats)
    if (s_last) {
        const float4* p4 = (const float4*)g_partials;
        float v = 0.0f;
        int nf4 = NBLOCKS / 4;                     // 185
        for (int k = tid; k < nf4; k += NTHREADS) {
            float4 q = p4[k];
            v += (q.x + q.y) + (q.z + q.w);
        }
        for (int off = 16; off > 0; off >>= 1)
            v += __shfl_down_sync(0xFFFFFFFFu, v, off);
        if (lane == 0) s_warp[warp] = v;
        __syncthreads();
        if (warp == 0) {
            float r = (lane < NWARPS) ? s_warp[lane] : 0.0f;
            for (int off = 2; off > 0; off >>= 1)
                r += __shfl_down_sync(0xFFFFFFFFu, r, off);
            if (lane == 0) {
                out[0] = r / (float)n;
                g_count = 0;   // reset for next graph replay
            }
        }
    }
}

extern "C" void kernel_launch(void* const* d_in, const int* in_sizes, int n_in,
                              void* d_out, int out_size)
{
    const float* pred   = (const float*)d_in[0];
    const float* target = (const float*)d_in[1];
    const float* weight = (const float*)d_in[2];
    float* out = (float*)d_out;

    int n = in_sizes[2];  // weight has N elements

    gwd_fused_kernel<<<NBLOCKS, NTHREADS>>>(pred, target, weight, out, n);
}

// round 15
// speedup vs baseline: 1.1800x; 1.1025x over previous
#include <cuda_runtime.h>
#include <math.h>

// GWD loss, single fused kernel — FINAL (R11 winner, best observed 12.8us):
//  - warp-private double-buffered cp.async, 128-row chunks (stage 5632B),
//    11 coalesced 16B cp.async per lane, no __syncthreads in hot loop
//  - 45KB smem/block -> 5 blocks/SM, grid 740 = one wave
//  - reduced row math: tr(St Sp) = 2SpSt + 2DpDt cos(2(rp-rt)) -> ONE __cosf;
//    sqrt(u)/prod^(1/4) = sqrt(u*rsqrt(prod)); approx MUFU ops throughout
//  - block reduce -> g_partials; last finished block reduces, writes mean
//  Achieved: 88MB @ ~6.9TB/s (86% of HBM spec) -> roofline-adjacent.

#define NBLOCKS   740    // 148 SMs * 5 (45KB smem/block)
#define NTHREADS  128    // 4 warps
#define NWARPS    4
#define WCHUNK    128    // rows per warp-iteration
#define STAGE_F4  352    // pred 160 + targ 160 + wgt 32

__device__ float g_partials[NBLOCKS];
__device__ unsigned int g_count = 0;

__device__ __forceinline__ float f_sqrt(float x) {
    float r; asm("sqrt.approx.f32 %0, %1;" : "=f"(r) : "f"(x)); return r;
}
__device__ __forceinline__ float f_rsqrt(float x) {
    float r; asm("rsqrt.approx.f32 %0, %1;" : "=f"(r) : "f"(x)); return r;
}
__device__ __forceinline__ float f_rcp(float x) {
    float r; asm("rcp.approx.f32 %0, %1;" : "=f"(r) : "f"(x)); return r;
}
__device__ __forceinline__ float f_lg2(float x) {
    float r; asm("lg2.approx.f32 %0, %1;" : "=f"(r) : "f"(x)); return r;
}

__device__ __forceinline__ void cp16(float4* smem, const float4* gmem) {
    unsigned saddr = (unsigned)__cvta_generic_to_shared(smem);
    asm volatile("cp.async.cg.shared.global [%0], [%1], 16;\n"
                 :: "r"(saddr), "l"(gmem));
}

__device__ __forceinline__ float row_loss(
    float xp, float yp, float wp, float hp, float rp,
    float xt, float yt, float wt, float ht, float rt,
    float wgt)
{
    float dx = xp - xt, dy = yp - yt;
    float xyd = dx * dx + dy * dy;

    float wp2 = wp * wp, hp2 = hp * hp;
    float wt2 = wt * wt, ht2 = ht * ht;

    float Sp = 0.125f * (wp2 + hp2);    // tr(Sigma_p)/2
    float Dp = 0.125f * (wp2 - hp2);
    float St = 0.125f * (wt2 + ht2);
    float Dt = 0.125f * (wt2 - ht2);

    float cosd = __cosf(2.0f * (rp - rt));
    // tr(Sigma_t Sigma_p):
    float trcross = 2.0f * (Sp * St + Dp * Dt * cosd);

    float prod4 = fabsf(wp * hp * wt * ht);
    // inner = trcross + 2*sqrt(det(cross)) = trcross + prod4/8
    float inner = fmaxf(trcross + 0.125f * prod4, 0.0f);

    // whr = tr_p + tr_t - 2*sqrt(inner) = 2(Sp+St) - 2*sqrt(inner)
    float whr = 2.0f * ((Sp + St) - f_sqrt(inner));

    float u = fmaxf(xyd + whr, 0.0f);
    // dist = sqrt(u)/prod4^(1/4) = sqrt(u * rsqrt(prod4))
    float dist = f_sqrt(u * f_rsqrt(prod4));

    float ln1p = f_lg2(1.0f + dist) * 0.6931471805599453f;
    float loss = 1.0f - f_rcp(1.0f + ln1p);
    return loss * wgt;
}

__global__ __launch_bounds__(NTHREADS, 5)
void gwd_fused_kernel(const float* __restrict__ pred,
                      const float* __restrict__ target,
                      const float* __restrict__ weight,
                      float* __restrict__ out,
                      int n)
{
    // per warp, per stage: [0..159]=pred f4, [160..319]=targ f4, [320..351]=wgt f4
    __shared__ float4 s_buf[NWARPS][2][STAGE_F4];   // 45,056 B

    const int tid  = threadIdx.x;
    const int lane = tid & 31;
    const int warp = tid >> 5;

    const int gw = blockIdx.x * NWARPS + warp;   // global warp id
    const int W  = gridDim.x * NWARPS;           // total warps
    const int nchunks = n / WCHUNK;              // 15625 for N=2M (exact)

    float acc = 0.0f;

    auto issue = [&](int c, float4* b) {
        const float4* gp  = (const float4*)(pred   + (long)c * WCHUNK * 5);
        const float4* gt  = (const float4*)(target + (long)c * WCHUNK * 5);
        const float4* gwt = (const float4*)(weight + (long)c * WCHUNK);
        #pragma unroll
        for (int k = 0; k < 5; k++)
            cp16(&b[k * 32 + lane], &gp[k * 32 + lane]);
        #pragma unroll
        for (int k = 0; k < 5; k++)
            cp16(&b[160 + k * 32 + lane], &gt[k * 32 + lane]);
        cp16(&b[320 + lane], &gwt[lane]);
    };

    int c = gw;
    if (c < nchunks) issue(c, s_buf[warp][0]);
    asm volatile("cp.async.commit_group;\n" ::: "memory");

    int s = 0;
    for (; c < nchunks; c += W)
    {
        int cn = c + W;
        float4* cur = s_buf[warp][s];
        float4* nxt = s_buf[warp][s ^ 1];
        if (cn < nchunks) issue(cn, nxt);
        asm volatile("cp.async.commit_group;\n" ::: "memory");
        asm volatile("cp.async.wait_group 1;\n" ::: "memory");
        __syncwarp();   // cross-lane visibility of cur

        const float* base = (const float*)cur;
        #pragma unroll
        for (int k = 0; k < 4; k++) {
            int r = k * 32 + lane;                 // conflict-free stride-5
            const float* p = base + 5 * r;
            const float* t = base + 640 + 5 * r;
            float wgt = base[1280 + r];
            acc += row_loss(p[0], p[1], p[2], p[3], p[4],
                            t[0], t[1], t[2], t[3], t[4], wgt);
        }
        __syncwarp();   // done reading cur before it's re-issued
        s ^= 1;
    }

    // tail rows (none for N=2M, kept for generality): block 0 scalar
    int tail_start = nchunks * WCHUNK;
    if (blockIdx.x == 0 && tail_start + tid < n) {
        int i = tail_start + tid;
        const float* p = pred + 5 * (long)i;
        const float* t = target + 5 * (long)i;
        acc += row_loss(p[0], p[1], p[2], p[3], p[4],
                        t[0], t[1], t[2], t[3], t[4], weight[i]);
    }

    // block reduction (barriers only here, outside hot loop)
    __shared__ float s_warp[NWARPS];
    for (int off = 16; off > 0; off >>= 1)
        acc += __shfl_down_sync(0xFFFFFFFFu, acc, off);
    if (lane == 0) s_warp[warp] = acc;
    __syncthreads();

    __shared__ bool s_last;
    if (warp == 0) {
        float v = (lane < NWARPS) ? s_warp[lane] : 0.0f;
        for (int off = 2; off > 0; off >>= 1)
            v += __shfl_down_sync(0xFFFFFFFFu, v, off);
        if (lane == 0) {
            g_partials[blockIdx.x] = v;
            __threadfence();
            unsigned int done = atomicAdd(&g_count, 1u);
            s_last = (done == gridDim.x - 1);
        }
    }
    __syncthreads();

    // last block reduces all partials, vectorized (185 f4 = 740 floats)
    if (s_last) {
        const float4* p4 = (const float4*)g_partials;
        float v = 0.0f;
        int nf4 = NBLOCKS / 4;                     // 185
        for (int k = tid; k < nf4; k += NTHREADS) {
            float4 q = p4[k];
            v += (q.x + q.y) + (q.z + q.w);
        }
        for (int off = 16; off > 0; off >>= 1)
            v += __shfl_down_sync(0xFFFFFFFFu, v, off);
        if (lane == 0) s_warp[warp] = v;
        __syncthreads();
        if (warp == 0) {
            float r = (lane < NWARPS) ? s_warp[lane] : 0.0f;
            for (int off = 2; off > 0; off >>= 1)
                r += __shfl_down_sync(0xFFFFFFFFu, r, off);
            if (lane == 0) {
                out[0] = r / (float)n;
                g_count = 0;   // reset for next graph replay
            }
        }
    }
}

extern "C" void kernel_launch(void* const* d_in, const int* in_sizes, int n_in,
                              void* d_out, int out_size)
{
    const float* pred   = (const float*)d_in[0];
    const float* target = (const float*)d_in[1];
    const float* weight = (const float*)d_in[2];
    float* out = (float*)d_out;

    int n = in_sizes[2];  // weight has N elements

    gwd_fused_kernel<<<NBLOCKS, NTHREADS>>>(pred, target, weight, out, n);
}

// round 16
// speedup vs baseline: 1.1830x; 1.0025x over previous
#include <cuda_runtime.h>
#include <math.h>

// GWD loss, single fused kernel — FINAL (confirmed twice at 12.8us):
//  - warp-private double-buffered cp.async, 128-row chunks (stage 5632B),
//    11 coalesced 16B cp.async per lane, no __syncthreads in hot loop
//  - 45KB smem/block -> 5 blocks/SM, grid 740 = one wave
//  - reduced row math: tr(St Sp) = 2SpSt + 2DpDt cos(2(rp-rt)) -> ONE __cosf;
//    sqrt(u)/prod^(1/4) = sqrt(u*rsqrt(prod)); approx MUFU ops throughout
//  - block reduce -> g_partials; last finished block reduces, writes mean
//  Achieved: 88MB @ ~6.9TB/s (86% of HBM spec) -> roofline-adjacent.

#define NBLOCKS   740    // 148 SMs * 5 (45KB smem/block)
#define NTHREADS  128    // 4 warps
#define NWARPS    4
#define WCHUNK    128    // rows per warp-iteration
#define STAGE_F4  352    // pred 160 + targ 160 + wgt 32

__device__ float g_partials[NBLOCKS];
__device__ unsigned int g_count = 0;

__device__ __forceinline__ float f_sqrt(float x) {
    float r; asm("sqrt.approx.f32 %0, %1;" : "=f"(r) : "f"(x)); return r;
}
__device__ __forceinline__ float f_rsqrt(float x) {
    float r; asm("rsqrt.approx.f32 %0, %1;" : "=f"(r) : "f"(x)); return r;
}
__device__ __forceinline__ float f_rcp(float x) {
    float r; asm("rcp.approx.f32 %0, %1;" : "=f"(r) : "f"(x)); return r;
}
__device__ __forceinline__ float f_lg2(float x) {
    float r; asm("lg2.approx.f32 %0, %1;" : "=f"(r) : "f"(x)); return r;
}

__device__ __forceinline__ void cp16(float4* smem, const float4* gmem) {
    unsigned saddr = (unsigned)__cvta_generic_to_shared(smem);
    asm volatile("cp.async.cg.shared.global [%0], [%1], 16;\n"
                 :: "r"(saddr), "l"(gmem));
}

__device__ __forceinline__ float row_loss(
    float xp, float yp, float wp, float hp, float rp,
    float xt, float yt, float wt, float ht, float rt,
    float wgt)
{
    float dx = xp - xt, dy = yp - yt;
    float xyd = dx * dx + dy * dy;

    float wp2 = wp * wp, hp2 = hp * hp;
    float wt2 = wt * wt, ht2 = ht * ht;

    float Sp = 0.125f * (wp2 + hp2);    // tr(Sigma_p)/2
    float Dp = 0.125f * (wp2 - hp2);
    float St = 0.125f * (wt2 + ht2);
    float Dt = 0.125f * (wt2 - ht2);

    float cosd = __cosf(2.0f * (rp - rt));
    // tr(Sigma_t Sigma_p):
    float trcross = 2.0f * (Sp * St + Dp * Dt * cosd);

    float prod4 = fabsf(wp * hp * wt * ht);
    // inner = trcross + 2*sqrt(det(cross)) = trcross + prod4/8
    float inner = fmaxf(trcross + 0.125f * prod4, 0.0f);

    // whr = tr_p + tr_t - 2*sqrt(inner) = 2(Sp+St) - 2*sqrt(inner)
    float whr = 2.0f * ((Sp + St) - f_sqrt(inner));

    float u = fmaxf(xyd + whr, 0.0f);
    // dist = sqrt(u)/prod4^(1/4) = sqrt(u * rsqrt(prod4))
    float dist = f_sqrt(u * f_rsqrt(prod4));

    float ln1p = f_lg2(1.0f + dist) * 0.6931471805599453f;
    float loss = 1.0f - f_rcp(1.0f + ln1p);
    return loss * wgt;
}

__global__ __launch_bounds__(NTHREADS, 5)
void gwd_fused_kernel(const float* __restrict__ pred,
                      const float* __restrict__ target,
                      const float* __restrict__ weight,
                      float* __restrict__ out,
                      int n)
{
    // per warp, per stage: [0..159]=pred f4, [160..319]=targ f4, [320..351]=wgt f4
    __shared__ float4 s_buf[NWARPS][2][STAGE_F4];   // 45,056 B

    const int tid  = threadIdx.x;
    const int lane = tid & 31;
    const int warp = tid >> 5;

    const int gw = blockIdx.x * NWARPS + warp;   // global warp id
    const int W  = gridDim.x * NWARPS;           // total warps
    const int nchunks = n / WCHUNK;              // 15625 for N=2M (exact)

    float acc = 0.0f;

    auto issue = [&](int c, float4* b) {
        const float4* gp  = (const float4*)(pred   + (long)c * WCHUNK * 5);
        const float4* gt  = (const float4*)(target + (long)c * WCHUNK * 5);
        const float4* gwt = (const float4*)(weight + (long)c * WCHUNK);
        #pragma unroll
        for (int k = 0; k < 5; k++)
            cp16(&b[k * 32 + lane], &gp[k * 32 + lane]);
        #pragma unroll
        for (int k = 0; k < 5; k++)
            cp16(&b[160 + k * 32 + lane], &gt[k * 32 + lane]);
        cp16(&b[320 + lane], &gwt[lane]);
    };

    int c = gw;
    if (c < nchunks) issue(c, s_buf[warp][0]);
    asm volatile("cp.async.commit_group;\n" ::: "memory");

    int s = 0;
    for (; c < nchunks; c += W)
    {
        int cn = c + W;
        float4* cur = s_buf[warp][s];
        float4* nxt = s_buf[warp][s ^ 1];
        if (cn < nchunks) issue(cn, nxt);
        asm volatile("cp.async.commit_group;\n" ::: "memory");
        asm volatile("cp.async.wait_group 1;\n" ::: "memory");
        __syncwarp();   // cross-lane visibility of cur

        const float* base = (const float*)cur;
        #pragma unroll
        for (int k = 0; k < 4; k++) {
            int r = k * 32 + lane;                 // conflict-free stride-5
            const float* p = base + 5 * r;
            const float* t = base + 640 + 5 * r;
            float wgt = base[1280 + r];
            acc += row_loss(p[0], p[1], p[2], p[3], p[4],
                            t[0], t[1], t[2], t[3], t[4], wgt);
        }
        __syncwarp();   // done reading cur before it's re-issued
        s ^= 1;
    }

    // tail rows (none for N=2M, kept for generality): block 0 scalar
    int tail_start = nchunks * WCHUNK;
    if (blockIdx.x == 0 && tail_start + tid < n) {
        int i = tail_start + tid;
        const float* p = pred + 5 * (long)i;
        const float* t = target + 5 * (long)i;
        acc += row_loss(p[0], p[1], p[2], p[3], p[4],
                        t[0], t[1], t[2], t[3], t[4], weight[i]);
    }

    // block reduction (barriers only here, outside hot loop)
    __shared__ float s_warp[NWARPS];
    for (int off = 16; off > 0; off >>= 1)
        acc += __shfl_down_sync(0xFFFFFFFFu, acc, off);
    if (lane == 0) s_warp[warp] = acc;
    __syncthreads();

    __shared__ bool s_last;
    if (warp == 0) {
        float v = (lane < NWARPS) ? s_warp[lane] : 0.0f;
        for (int off = 2; off > 0; off >>= 1)
            v += __shfl_down_sync(0xFFFFFFFFu, v, off);
        if (lane == 0) {
            g_partials[blockIdx.x] = v;
            __threadfence();
            unsigned int done = atomicAdd(&g_count, 1u);
            s_last = (done == gridDim.x - 1);
        }
    }
    __syncthreads();

    // last block reduces all partials, vectorized (185 f4 = 740 floats)
    if (s_last) {
        const float4* p4 = (const float4*)g_partials;
        float v = 0.0f;
        int nf4 = NBLOCKS / 4;                     // 185
        for (int k = tid; k < nf4; k += NTHREADS) {
            float4 q = p4[k];
            v += (q.x + q.y) + (q.z + q.w);
        }
        for (int off = 16; off > 0; off >>= 1)
            v += __shfl_down_sync(0xFFFFFFFFu, v, off);
        if (lane == 0) s_warp[warp] = v;
        __syncthreads();
        if (warp == 0) {
            float r = (lane < NWARPS) ? s_warp[lane] : 0.0f;
            for (int off = 2; off > 0; off >>= 1)
                r += __shfl_down_sync(0xFFFFFFFFu, r, off);
            if (lane == 0) {
                out[0] = r / (float)n;
                g_count = 0;   // reset for next graph replay
            }
        }
    }
}

extern "C" void kernel_launch(void* const* d_in, const int* in_sizes, int n_in,
                              void* d_out, int out_size)
{
    const float* pred   = (const float*)d_in[0];
    const float* target = (const float*)d_in[1];
    const float* weight = (const float*)d_in[2];
    float* out = (float*)d_out;

    int n = in_sizes[2];  // weight has N elements

    gwd_fused_kernel<<<NBLOCKS, NTHREADS>>>(pred, target, weight, out, n);
}